// round 6
// baseline (speedup 1.0000x reference)
#include <cuda_runtime.h>
#include <cuda_fp16.h>
#include <cstdint>

// Problem constants: F=50000, K=32, E=128, N_NODE=100000
#define KNBR 32
#define EMB  128
#define MAXF 50000
#define MAXN 100000

// Scratch (no cudaMalloc allowed)
__device__ float g_agg[MAXF * EMB];                        // 25.6 MB fp32
__device__ float g_p[MAXN];                                // 0.4 MB
__device__ alignas(16) __half g_emb_h [MAXN * EMB];        // 25.6 MB
__device__ alignas(16) __half g_embf_h[MAXF * EMB];        // 12.8 MB
__device__ alignas(16) __half g_aggh  [MAXF * EMB];        // 12.8 MB

// ---------------------------------------------------------------------------
// PTX helpers
// ---------------------------------------------------------------------------
__device__ __forceinline__ void ldsm_x4(uint32_t& r0, uint32_t& r1,
                                        uint32_t& r2, uint32_t& r3, uint32_t a)
{
    asm volatile("ldmatrix.sync.aligned.m8n8.x4.shared.b16 {%0,%1,%2,%3}, [%4];"
                 : "=r"(r0), "=r"(r1), "=r"(r2), "=r"(r3) : "r"(a));
}
__device__ __forceinline__ void ldsm_x4_t(uint32_t& r0, uint32_t& r1,
                                          uint32_t& r2, uint32_t& r3, uint32_t a)
{
    asm volatile("ldmatrix.sync.aligned.m8n8.x4.trans.shared.b16 {%0,%1,%2,%3}, [%4];"
                 : "=r"(r0), "=r"(r1), "=r"(r2), "=r"(r3) : "r"(a));
}
__device__ __forceinline__ void mma16816(float* d, const uint32_t* a,
                                         uint32_t b0, uint32_t b1)
{
    asm volatile(
        "mma.sync.aligned.m16n8k16.row.col.f32.f16.f16.f32 "
        "{%0,%1,%2,%3}, {%4,%5,%6,%7}, {%8,%9}, {%0,%1,%2,%3};"
        : "+f"(d[0]), "+f"(d[1]), "+f"(d[2]), "+f"(d[3])
        : "r"(a[0]), "r"(a[1]), "r"(a[2]), "r"(a[3]), "r"(b0), "r"(b1));
}
__device__ __forceinline__ void cp_async16(uint32_t saddr, const void* gaddr)
{
    asm volatile("cp.async.cg.shared.global [%0], [%1], 16;"
                 :: "r"(saddr), "l"(gaddr));
}

// ---------------------------------------------------------------------------
// Kernel PRE: blocks [0, nblk_p): p[n] = dot(emb_i[n], u) + fp16 copy of emb_i
//             blocks [nblk_p, ..): fp16 copy of emb_f
// ---------------------------------------------------------------------------
__global__ __launch_bounds__(256) void pre_kernel(
    const float* __restrict__ emb_i, const float* __restrict__ emb_f,
    const float* __restrict__ u, int N, int F, int nblk_p)
{
    if (blockIdx.x < (unsigned)nblk_p) {
        int gw   = (blockIdx.x * 256 + threadIdx.x) >> 5;
        int lane = threadIdx.x & 31;
        if (gw >= N) return;
        float4 v  = *reinterpret_cast<const float4*>(emb_i + (size_t)gw * EMB + lane * 4);
        float4 uu = *reinterpret_cast<const float4*>(u + lane * 4);

        __half2 h0 = __float22half2_rn(make_float2(v.x, v.y));
        __half2 h1 = __float22half2_rn(make_float2(v.z, v.w));
        uint2 hw;
        hw.x = *reinterpret_cast<uint32_t*>(&h0);
        hw.y = *reinterpret_cast<uint32_t*>(&h1);
        *reinterpret_cast<uint2*>(&g_emb_h[(size_t)gw * EMB + lane * 4]) = hw;

        float s = v.x * uu.x + v.y * uu.y + v.z * uu.z + v.w * uu.w;
#pragma unroll
        for (int off = 16; off > 0; off >>= 1)
            s += __shfl_xor_sync(0xffffffffu, s, off);
        if (lane == 0) g_p[gw] = s;
    } else {
        int id = (blockIdx.x - nblk_p) * 256 + threadIdx.x;   // float4 index
        size_t base = (size_t)id * 4;
        if (base >= (size_t)F * EMB) return;
        float4 v = *reinterpret_cast<const float4*>(emb_f + base);
        __half2 h0 = __float22half2_rn(make_float2(v.x, v.y));
        __half2 h1 = __float22half2_rn(make_float2(v.z, v.w));
        uint2 hw;
        hw.x = *reinterpret_cast<uint32_t*>(&h0);
        hw.y = *reinterpret_cast<uint32_t*>(&h1);
        *reinterpret_cast<uint2*>(&g_embf_h[base]) = hw;
    }
}

// ---------------------------------------------------------------------------
// Kernel B: fused softmax + aggregate, warp per feature.
// agg[f,e] = sum_k softmax_k(p[adj[f,k]]+mask) * emb_h[adj[f,k], e]
// Lane k holds (idx_k, alpha_k); gather loop broadcasts via shfl.
// Each lane gathers 8B (4 halves) per neighbor -> 256B/warp, 32-deep MLP.
// Writes fp32 g_agg (epilogue) and fp16 g_aggh (GEMM input).
// ---------------------------------------------------------------------------
__global__ __launch_bounds__(256) void agg_kernel(
    const int* __restrict__ adj, int F)
{
    const int f    = blockIdx.x * 8 + (threadIdx.x >> 5);
    const int lane = threadIdx.x & 31;
    if (f >= F) return;

    int   idx = adj[(size_t)f * KNBR + lane];
    float a = g_p[idx] + (idx != 0 ? 0.0f : -10000.0f);
    float m = a;
#pragma unroll
    for (int off = 16; off > 0; off >>= 1)
        m = fmaxf(m, __shfl_xor_sync(0xffffffffu, m, off));
    float e = __expf(a - m);
    float sum = e;
#pragma unroll
    for (int off = 16; off > 0; off >>= 1)
        sum += __shfl_xor_sync(0xffffffffu, sum, off);
    float al = e / sum;

    const uint2* base = reinterpret_cast<const uint2*>(g_emb_h);
    float4 acc = make_float4(0.0f, 0.0f, 0.0f, 0.0f);
#pragma unroll
    for (int k = 0; k < KNBR; k++) {
        int   row = __shfl_sync(0xffffffffu, idx, k);
        float ak  = __shfl_sync(0xffffffffu, al,  k);
        uint2 hv  = __ldg(base + (size_t)((unsigned)row) * (EMB / 4) + lane);
        __half2 h0 = *reinterpret_cast<__half2*>(&hv.x);
        __half2 h1 = *reinterpret_cast<__half2*>(&hv.y);
        float2 v0 = __half22float2(h0);
        float2 v1 = __half22float2(h1);
        acc.x = fmaf(ak, v0.x, acc.x);
        acc.y = fmaf(ak, v0.y, acc.y);
        acc.z = fmaf(ak, v1.x, acc.z);
        acc.w = fmaf(ak, v1.y, acc.w);
    }
    *reinterpret_cast<float4*>(&g_agg[(size_t)f * EMB + lane * 4]) = acc;

    __half2 o0 = __float22half2_rn(make_float2(acc.x, acc.y));
    __half2 o1 = __float22half2_rn(make_float2(acc.z, acc.w));
    uint2 ow;
    ow.x = *reinterpret_cast<uint32_t*>(&o0);
    ow.y = *reinterpret_cast<uint32_t*>(&o1);
    *reinterpret_cast<uint2*>(&g_aggh[(size_t)f * EMB + lane * 4]) = ow;
}

// ---------------------------------------------------------------------------
// Kernel C: tensor-core gate+fuse, persistent, cp.async double-buffered fp16
// cat tiles. gate = sigmoid(cat([emb_f, agg]) @ W.T + b);
// out = gate*emb_f + (1-gate)*agg (fp32 epilogue reads).
// 256 threads = 8 warps (4f x 2e); warp tile 16f x 64e; K=256 in 16 steps.
// ---------------------------------------------------------------------------
#define TM 64
#define W_LDH   136                      // halves per k-row (128 + 8 pad)
#define CAT_LDH 264                      // halves per f-row (256 + 8 pad)
#define S_W_HALFS    (256 * W_LDH)       // 34816 halves = 69632 B
#define S_CAT_HALFS  (TM * CAT_LDH)      // 16896 halves = 33792 B
#define S_CAT_BYTES  (S_CAT_HALFS * 2)
#define SMEM_GATE_B  (S_W_HALFS * 2 + 2 * S_CAT_BYTES)   // 137216 B

__global__ __launch_bounds__(256, 1) void gate_fuse_kernel(
    const float* __restrict__ emb_f,  // [F, 128] fp32 (epilogue)
    const float* __restrict__ W,      // [128, 256]
    const float* __restrict__ bias,   // [128]
    float* __restrict__ out,          // [F, 128]
    int F)
{
    extern __shared__ __half hsmem[];
    __half* s_w   = hsmem;                 // [k=0..255][n=0..127] (+pad)
    __half* s_cat = hsmem + S_W_HALFS;     // 2 x [f=0..63][k=0..255] (+pad)

    const int t    = threadIdx.x;
    const int lane = t & 31;
    const int wid  = t >> 5;
    const int f0   = (wid >> 1) * 16;
    const int nb   = (wid & 1) * 64;
    const int ntiles = (F + TM - 1) / TM;

    // ---- W -> fp16 smem [k][n] transposed, once per block (float4 loads) ----
#pragma unroll
    for (int r = 0; r < 32; r++) {
        int id = t + 256 * r;             // 8192 float4 = 128e x 64jq
        int e  = id >> 6;                 // 0..127
        int jq = id & 63;                 // j = jq*4..jq*4+3
        float4 v = *reinterpret_cast<const float4*>(W + e * 256 + jq * 4);
        s_w[(jq * 4 + 0) * W_LDH + e] = __float2half_rn(v.x);
        s_w[(jq * 4 + 1) * W_LDH + e] = __float2half_rn(v.y);
        s_w[(jq * 4 + 2) * W_LDH + e] = __float2half_rn(v.z);
        s_w[(jq * 4 + 3) * W_LDH + e] = __float2half_rn(v.w);
    }
    __syncthreads();

    const uint32_t s_cat_u = (uint32_t)__cvta_generic_to_shared(s_cat);
    const uint32_t s_w_u   = (uint32_t)__cvta_generic_to_shared(s_w);

    // ldmatrix lane addresses
    uint32_t a_addr[2];
#pragma unroll
    for (int b = 0; b < 2; b++)
        a_addr[b] = s_cat_u + (uint32_t)b * S_CAT_BYTES +
            (uint32_t)(((f0 + (lane & 15)) * CAT_LDH + (lane >> 4) * 8) * 2);
    const uint32_t b_lane_addr = s_w_u +
        (uint32_t)(((((lane >> 3) & 1) * 8 + (lane & 7)) * W_LDH
                    + nb + (lane >> 4) * 8) * 2);

    // prefetch cat tile: 64 rows x 32 chunks of 16B (8 halves) = full 256 halves/row
    auto prefetch = [&](int tile, int buf) {
        int fbase = tile * TM;
#pragma unroll
        for (int r = 0; r < 8; r++) {
            int id  = t + 256 * r;         // 2048 chunks
            int row = id >> 5;             // 0..63
            int c   = id & 31;             // chunk within row, 0..31
            int gf  = fbase + row; if (gf >= F) gf = F - 1;
            const __half* src = (c < 16)
                ? (g_embf_h + (size_t)gf * EMB + c * 8)
                : (g_aggh   + (size_t)gf * EMB + (c - 16) * 8);
            uint32_t dst = s_cat_u + (uint32_t)buf * S_CAT_BYTES +
                           (uint32_t)((row * CAT_LDH + c * 8) * 2);
            cp_async16(dst, src);
        }
    };

    const int tile0 = blockIdx.x;
    if (tile0 < ntiles) prefetch(tile0, 0);
    asm volatile("cp.async.commit_group;");

    int buf = 0;
#pragma unroll 1
    for (int tile = tile0; tile < ntiles; tile += gridDim.x, buf ^= 1) {
        int nt = tile + gridDim.x;
        if (nt < ntiles) prefetch(nt, buf ^ 1);
        asm volatile("cp.async.commit_group;");
        asm volatile("cp.async.wait_group 1;" ::: "memory");
        __syncthreads();

        // ---- MMA mainloop over K=256 ----
        float acc[32];
#pragma unroll
        for (int i = 0; i < 32; i++) acc[i] = 0.0f;

#pragma unroll
        for (int ks = 0; ks < 16; ks++) {
            const int k0 = ks * 16;
            uint32_t a[4];
            ldsm_x4(a[0], a[1], a[2], a[3], a_addr[buf] + (uint32_t)(k0 * 2));
#pragma unroll
            for (int np = 0; np < 4; np++) {
                uint32_t b0, b1, b2, b3;
                ldsm_x4_t(b0, b1, b2, b3,
                          b_lane_addr + (uint32_t)((k0 * W_LDH + np * 16) * 2));
                mma16816(&acc[(np * 2 + 0) * 4], a, b0, b1);
                mma16816(&acc[(np * 2 + 1) * 4], a, b2, b3);
            }
        }
        __syncthreads();   // all reads of buf done before next prefetch overwrites

        // ---- Epilogue: gate + blend (fp32) ----
        const int fbase = tile * TM;
        const int r  = lane >> 2;
        const int cq = (lane & 3) * 2;
#pragma unroll
        for (int ti = 0; ti < 8; ti++) {
            int c = nb + ti * 8 + cq;
            float2 b2v = *reinterpret_cast<const float2*>(bias + c);
#pragma unroll
            for (int h = 0; h < 2; h++) {
                int f = fbase + f0 + r + 8 * h;
                if (f >= F) continue;
                float x0 = acc[ti * 4 + 2 * h]     + b2v.x;
                float x1 = acc[ti * 4 + 2 * h + 1] + b2v.y;
                float g0 = 1.0f / (1.0f + __expf(-x0));
                float g1 = 1.0f / (1.0f + __expf(-x1));
                float2 ef = *reinterpret_cast<const float2*>(emb_f + (size_t)f * EMB + c);
                float2 ag = *reinterpret_cast<const float2*>(g_agg + (size_t)f * EMB + c);
                float2 o;
                o.x = g0 * ef.x + (1.0f - g0) * ag.x;
                o.y = g1 * ef.y + (1.0f - g1) * ag.y;
                *reinterpret_cast<float2*>(out + (size_t)f * EMB + c) = o;
            }
        }
    }
}

// ---------------------------------------------------------------------------
extern "C" void kernel_launch(void* const* d_in, const int* in_sizes, int n_in,
                              void* d_out, int out_size)
{
    const int*   adj   = (const int*)d_in[0];     // [F,32]
    const float* emb_i = (const float*)d_in[1];   // [N,128]
    const float* emb_f = (const float*)d_in[2];   // [F,128]
    const float* u     = (const float*)d_in[3];   // [128]
    const float* W     = (const float*)d_in[4];   // [128,256]
    const float* bias  = (const float*)d_in[5];   // [128]
    float*       out   = (float*)d_out;           // [F,128]

    const int F = in_sizes[0] / KNBR;
    const int N = in_sizes[1] / EMB;

    int nsm = 148;
    cudaDeviceGetAttribute(&nsm, cudaDevAttrMultiProcessorCount, 0);

    cudaFuncSetAttribute(gate_fuse_kernel,
                         cudaFuncAttributeMaxDynamicSharedMemorySize, SMEM_GATE_B);

    int nblk_p = (N + 7) / 8;                       // warp per node
    int nblk_c = ((size_t)F * EMB / 4 + 255) / 256; // float4 per thread
    pre_kernel<<<nblk_p + nblk_c, 256>>>(emb_i, emb_f, u, N, F, nblk_p);

    agg_kernel<<<(F + 7) / 8, 256>>>(adj, F);

    int ntiles = (F + TM - 1) / TM;
    int nblk = ntiles < nsm ? ntiles : nsm;
    gate_fuse_kernel<<<nblk, 256, SMEM_GATE_B>>>(emb_f, W, bias, out, F);
}

// round 7
// speedup vs baseline: 1.1091x; 1.1091x over previous
#include <cuda_runtime.h>
#include <cuda_fp16.h>
#include <cstdint>

// Problem constants: F=50000, K=32, E=128, N_NODE=100000
#define KNBR 32
#define EMB  128
#define MAXF 50000
#define MAXN 100000

// Scratch (no cudaMalloc allowed)
__device__ float g_agg[MAXF * EMB];                        // 25.6 MB fp32
__device__ float g_p[MAXN];                                // 0.4 MB
__device__ alignas(16) __half g_emb_h [MAXN * EMB];        // 25.6 MB
__device__ alignas(16) __half g_embf_h[MAXF * EMB];        // 12.8 MB
__device__ alignas(16) __half g_aggh  [MAXF * EMB];        // 12.8 MB

// ---------------------------------------------------------------------------
// PTX helpers
// ---------------------------------------------------------------------------
__device__ __forceinline__ void ldsm_x4(uint32_t& r0, uint32_t& r1,
                                        uint32_t& r2, uint32_t& r3, uint32_t a)
{
    asm volatile("ldmatrix.sync.aligned.m8n8.x4.shared.b16 {%0,%1,%2,%3}, [%4];"
                 : "=r"(r0), "=r"(r1), "=r"(r2), "=r"(r3) : "r"(a));
}
__device__ __forceinline__ void ldsm_x4_t(uint32_t& r0, uint32_t& r1,
                                          uint32_t& r2, uint32_t& r3, uint32_t a)
{
    asm volatile("ldmatrix.sync.aligned.m8n8.x4.trans.shared.b16 {%0,%1,%2,%3}, [%4];"
                 : "=r"(r0), "=r"(r1), "=r"(r2), "=r"(r3) : "r"(a));
}
__device__ __forceinline__ void mma16816(float* d, const uint32_t* a,
                                         uint32_t b0, uint32_t b1)
{
    asm volatile(
        "mma.sync.aligned.m16n8k16.row.col.f32.f16.f16.f32 "
        "{%0,%1,%2,%3}, {%4,%5,%6,%7}, {%8,%9}, {%0,%1,%2,%3};"
        : "+f"(d[0]), "+f"(d[1]), "+f"(d[2]), "+f"(d[3])
        : "r"(a[0]), "r"(a[1]), "r"(a[2]), "r"(a[3]), "r"(b0), "r"(b1));
}
__device__ __forceinline__ void cp_async16(uint32_t saddr, const void* gaddr)
{
    asm volatile("cp.async.cg.shared.global [%0], [%1], 16;"
                 :: "r"(saddr), "l"(gaddr));
}

// ---------------------------------------------------------------------------
// Kernel PRE: blocks [0, nblk_p): p[n] = dot(emb_i[n], u) + fp16 copy of emb_i
//             blocks [nblk_p, ..): fp16 copy of emb_f
// ---------------------------------------------------------------------------
__global__ __launch_bounds__(256) void pre_kernel(
    const float* __restrict__ emb_i, const float* __restrict__ emb_f,
    const float* __restrict__ u, int N, int F, int nblk_p)
{
    if (blockIdx.x < (unsigned)nblk_p) {
        int gw   = (blockIdx.x * 256 + threadIdx.x) >> 5;
        int lane = threadIdx.x & 31;
        if (gw >= N) return;
        float4 v  = *reinterpret_cast<const float4*>(emb_i + (size_t)gw * EMB + lane * 4);
        float4 uu = *reinterpret_cast<const float4*>(u + lane * 4);

        __half2 h0 = __float22half2_rn(make_float2(v.x, v.y));
        __half2 h1 = __float22half2_rn(make_float2(v.z, v.w));
        uint2 hw;
        hw.x = *reinterpret_cast<uint32_t*>(&h0);
        hw.y = *reinterpret_cast<uint32_t*>(&h1);
        *reinterpret_cast<uint2*>(&g_emb_h[(size_t)gw * EMB + lane * 4]) = hw;

        float s = v.x * uu.x + v.y * uu.y + v.z * uu.z + v.w * uu.w;
#pragma unroll
        for (int off = 16; off > 0; off >>= 1)
            s += __shfl_xor_sync(0xffffffffu, s, off);
        if (lane == 0) g_p[gw] = s;
    } else {
        int id = (blockIdx.x - nblk_p) * 256 + threadIdx.x;   // float4 index
        size_t base = (size_t)id * 4;
        if (base >= (size_t)F * EMB) return;
        float4 v = *reinterpret_cast<const float4*>(emb_f + base);
        __half2 h0 = __float22half2_rn(make_float2(v.x, v.y));
        __half2 h1 = __float22half2_rn(make_float2(v.z, v.w));
        uint2 hw;
        hw.x = *reinterpret_cast<uint32_t*>(&h0);
        hw.y = *reinterpret_cast<uint32_t*>(&h1);
        *reinterpret_cast<uint2*>(&g_embf_h[base]) = hw;
    }
}

// ---------------------------------------------------------------------------
// Kernel B: fused softmax + aggregate, warp per feature.
// agg[f,e] = sum_k softmax_k(p[adj[f,k]]+mask) * emb_h[adj[f,k], e]
// Lane k holds (idx_k, alpha_k); gather loop broadcasts via shfl.
// Each lane gathers 8B (4 halves) per neighbor -> 256B/warp.
// unroll 8 bounds in-flight loads (MLP=8, no spills).
// Writes fp32 g_agg (epilogue) and fp16 g_aggh (GEMM input).
// ---------------------------------------------------------------------------
__global__ __launch_bounds__(256) void agg_kernel(
    const int* __restrict__ adj, int F)
{
    const int f    = blockIdx.x * 8 + (threadIdx.x >> 5);
    const int lane = threadIdx.x & 31;
    if (f >= F) return;

    int   idx = adj[(size_t)f * KNBR + lane];
    float a = g_p[idx] + (idx != 0 ? 0.0f : -10000.0f);
    float m = a;
#pragma unroll
    for (int off = 16; off > 0; off >>= 1)
        m = fmaxf(m, __shfl_xor_sync(0xffffffffu, m, off));
    float e = __expf(a - m);
    float sum = e;
#pragma unroll
    for (int off = 16; off > 0; off >>= 1)
        sum += __shfl_xor_sync(0xffffffffu, sum, off);
    float al = e / sum;

    const uint2* base = reinterpret_cast<const uint2*>(g_emb_h);
    float4 acc = make_float4(0.0f, 0.0f, 0.0f, 0.0f);
#pragma unroll 8
    for (int k = 0; k < KNBR; k++) {
        int   row = __shfl_sync(0xffffffffu, idx, k);
        float ak  = __shfl_sync(0xffffffffu, al,  k);
        uint2 hv  = __ldg(base + (size_t)((unsigned)row) * (EMB / 4) + lane);
        __half2 h0 = *reinterpret_cast<__half2*>(&hv.x);
        __half2 h1 = *reinterpret_cast<__half2*>(&hv.y);
        float2 v0 = __half22float2(h0);
        float2 v1 = __half22float2(h1);
        acc.x = fmaf(ak, v0.x, acc.x);
        acc.y = fmaf(ak, v0.y, acc.y);
        acc.z = fmaf(ak, v1.x, acc.z);
        acc.w = fmaf(ak, v1.y, acc.w);
    }
    *reinterpret_cast<float4*>(&g_agg[(size_t)f * EMB + lane * 4]) = acc;

    __half2 o0 = __float22half2_rn(make_float2(acc.x, acc.y));
    __half2 o1 = __float22half2_rn(make_float2(acc.z, acc.w));
    uint2 ow;
    ow.x = *reinterpret_cast<uint32_t*>(&o0);
    ow.y = *reinterpret_cast<uint32_t*>(&o1);
    *reinterpret_cast<uint2*>(&g_aggh[(size_t)f * EMB + lane * 4]) = ow;
}

// ---------------------------------------------------------------------------
// Kernel C: tensor-core gate+fuse, persistent, 2 CTAs/SM.
// Single fp16 cat buffer; next tile's cp.async prefetch issued between the
// MMA loop and the epilogue so its flight time hides under the epilogue.
// gate = sigmoid(cat([emb_f, agg]) @ W.T + b); out = gate*ef + (1-gate)*ag.
// 256 threads = 8 warps (4f x 2e); warp tile 16f x 64e; K=256 in 16 steps.
// ---------------------------------------------------------------------------
#define TM 64
#define W_LDH   136                      // halves per k-row (128 + 8 pad)
#define CAT_LDH 264                      // halves per f-row (256 + 8 pad)
#define S_W_HALFS    (256 * W_LDH)       // 34816 halves = 69632 B
#define S_CAT_HALFS  (TM * CAT_LDH)      // 16896 halves = 33792 B
#define SMEM_GATE_B  ((S_W_HALFS + S_CAT_HALFS) * 2)     // 103424 B

__global__ __launch_bounds__(256, 2) void gate_fuse_kernel(
    const float* __restrict__ emb_f,  // [F, 128] fp32 (epilogue)
    const float* __restrict__ W,      // [128, 256]
    const float* __restrict__ bias,   // [128]
    float* __restrict__ out,          // [F, 128]
    int F)
{
    extern __shared__ __half hsmem[];
    __half* s_w   = hsmem;                 // [k=0..255][n=0..127] (+pad)
    __half* s_cat = hsmem + S_W_HALFS;     // [f=0..63][k=0..255] (+pad)

    const int t    = threadIdx.x;
    const int lane = t & 31;
    const int wid  = t >> 5;
    const int f0   = (wid >> 1) * 16;
    const int nb   = (wid & 1) * 64;
    const int ntiles = (F + TM - 1) / TM;

    const uint32_t s_cat_u = (uint32_t)__cvta_generic_to_shared(s_cat);
    const uint32_t s_w_u   = (uint32_t)__cvta_generic_to_shared(s_w);

    // prefetch cat tile: 64 rows x 32 chunks of 16B (8 halves)
    auto prefetch = [&](int tile) {
        int fbase = tile * TM;
#pragma unroll
        for (int r = 0; r < 8; r++) {
            int id  = t + 256 * r;         // 2048 chunks
            int row = id >> 5;             // 0..63
            int c   = id & 31;             // chunk 0..31
            int gf  = fbase + row; if (gf >= F) gf = F - 1;
            const __half* src = (c < 16)
                ? (g_embf_h + (size_t)gf * EMB + c * 8)
                : (g_aggh   + (size_t)gf * EMB + (c - 16) * 8);
            uint32_t dst = s_cat_u + (uint32_t)((row * CAT_LDH + c * 8) * 2);
            cp_async16(dst, src);
        }
    };

    // Issue tile0 cat prefetch FIRST; it flies under the W load/convert.
    const int tile0 = blockIdx.x;
    if (tile0 < ntiles) prefetch(tile0);
    asm volatile("cp.async.commit_group;");

    // ---- W -> fp16 smem [k][n] transposed, once per block ----
#pragma unroll
    for (int r = 0; r < 32; r++) {
        int id = t + 256 * r;             // 8192 float4 = 128e x 64jq
        int e  = id >> 6;                 // 0..127
        int jq = id & 63;                 // j = jq*4..jq*4+3
        float4 v = *reinterpret_cast<const float4*>(W + e * 256 + jq * 4);
        s_w[(jq * 4 + 0) * W_LDH + e] = __float2half_rn(v.x);
        s_w[(jq * 4 + 1) * W_LDH + e] = __float2half_rn(v.y);
        s_w[(jq * 4 + 2) * W_LDH + e] = __float2half_rn(v.z);
        s_w[(jq * 4 + 3) * W_LDH + e] = __float2half_rn(v.w);
    }

    // ldmatrix lane addresses
    const uint32_t a_lane_addr = s_cat_u +
        (uint32_t)(((f0 + (lane & 15)) * CAT_LDH + (lane >> 4) * 8) * 2);
    const uint32_t b_lane_addr = s_w_u +
        (uint32_t)(((((lane >> 3) & 1) * 8 + (lane & 7)) * W_LDH
                    + nb + (lane >> 4) * 8) * 2);

#pragma unroll 1
    for (int tile = tile0; tile < ntiles; tile += gridDim.x) {
        // wait for this tile's cat (prefetched last iteration / at entry)
        asm volatile("cp.async.wait_group 0;" ::: "memory");
        __syncthreads();

        // ---- MMA mainloop over K=256 ----
        float acc[32];
#pragma unroll
        for (int i = 0; i < 32; i++) acc[i] = 0.0f;

#pragma unroll
        for (int ks = 0; ks < 16; ks++) {
            const int k0 = ks * 16;
            uint32_t a[4];
            ldsm_x4(a[0], a[1], a[2], a[3], a_lane_addr + (uint32_t)(k0 * 2));
#pragma unroll
            for (int np = 0; np < 4; np++) {
                uint32_t b0, b1, b2, b3;
                ldsm_x4_t(b0, b1, b2, b3,
                          b_lane_addr + (uint32_t)((k0 * W_LDH + np * 16) * 2));
                mma16816(&acc[(np * 2 + 0) * 4], a, b0, b1);
                mma16816(&acc[(np * 2 + 1) * 4], a, b2, b3);
            }
        }
        __syncthreads();   // all warps done reading s_cat

        // issue next tile's prefetch; flight hides under the epilogue
        int nt = tile + gridDim.x;
        if (nt < ntiles) prefetch(nt);
        asm volatile("cp.async.commit_group;");

        // ---- Epilogue: gate + blend (fp32 global reads) ----
        const int fbase = tile * TM;
        const int r  = lane >> 2;
        const int cq = (lane & 3) * 2;
#pragma unroll
        for (int ti = 0; ti < 8; ti++) {
            int c = nb + ti * 8 + cq;
            float2 b2v = *reinterpret_cast<const float2*>(bias + c);
#pragma unroll
            for (int h = 0; h < 2; h++) {
                int f = fbase + f0 + r + 8 * h;
                if (f >= F) continue;
                float x0 = acc[ti * 4 + 2 * h]     + b2v.x;
                float x1 = acc[ti * 4 + 2 * h + 1] + b2v.y;
                float g0 = 1.0f / (1.0f + __expf(-x0));
                float g1 = 1.0f / (1.0f + __expf(-x1));
                float2 ef = *reinterpret_cast<const float2*>(emb_f + (size_t)f * EMB + c);
                float2 ag = *reinterpret_cast<const float2*>(g_agg + (size_t)f * EMB + c);
                float2 o;
                o.x = g0 * ef.x + (1.0f - g0) * ag.x;
                o.y = g1 * ef.y + (1.0f - g1) * ag.y;
                *reinterpret_cast<float2*>(out + (size_t)f * EMB + c) = o;
            }
        }
    }
}

// ---------------------------------------------------------------------------
extern "C" void kernel_launch(void* const* d_in, const int* in_sizes, int n_in,
                              void* d_out, int out_size)
{
    const int*   adj   = (const int*)d_in[0];     // [F,32]
    const float* emb_i = (const float*)d_in[1];   // [N,128]
    const float* emb_f = (const float*)d_in[2];   // [F,128]
    const float* u     = (const float*)d_in[3];   // [128]
    const float* W     = (const float*)d_in[4];   // [128,256]
    const float* bias  = (const float*)d_in[5];   // [128]
    float*       out   = (float*)d_out;           // [F,128]

    const int F = in_sizes[0] / KNBR;
    const int N = in_sizes[1] / EMB;

    int nsm = 148;
    cudaDeviceGetAttribute(&nsm, cudaDevAttrMultiProcessorCount, 0);

    cudaFuncSetAttribute(gate_fuse_kernel,
                         cudaFuncAttributeMaxDynamicSharedMemorySize, SMEM_GATE_B);

    int nblk_p = (N + 7) / 8;                       // warp per node
    int nblk_c = ((size_t)F * EMB / 4 + 255) / 256; // float4 per thread
    pre_kernel<<<nblk_p + nblk_c, 256>>>(emb_i, emb_f, u, N, F, nblk_p);

    agg_kernel<<<(F + 7) / 8, 256>>>(adj, F);

    int ntiles = (F + TM - 1) / TM;
    int nblk = 2 * nsm;
    if (nblk > ntiles) nblk = ntiles;
    gate_fuse_kernel<<<nblk, 256, SMEM_GATE_B>>>(emb_f, W, bias, out, F);
}